// round 12
// baseline (speedup 1.0000x reference)
#include <cuda_runtime.h>
#include <cstdint>

#define BQ 16384
#define EE 8
#define CC 1000
#define DD 59
#define H1N 256
#define H2N 128
#define EPSF 1e-8f
#define LN_EPSF 1e-5f
#define MROWS 16
#define LN2F 0.69314718055994530942f
#define FEAT_BLOCKS 444
#define FEAT_SMEM 72960

typedef unsigned long long u64;

__device__ __forceinline__ float wsum(float v) {
    #pragma unroll
    for (int o = 16; o; o >>= 1) v += __shfl_xor_sync(0xffffffffu, v, o);
    return v;
}

// ---- f32x2 packed helpers (sm_100+) ----
__device__ __forceinline__ u64 pk2(float a, float b) {
    u64 r; asm("mov.b64 %0, {%1, %2};" : "=l"(r) : "f"(a), "f"(b)); return r;
}
__device__ __forceinline__ void upk2(u64 v, float& a, float& b) {
    asm("mov.b64 {%0, %1}, %2;" : "=f"(a), "=f"(b) : "l"(v));
}
__device__ __forceinline__ u64 fma2(u64 a, u64 b, u64 c) {
    u64 d; asm("fma.rn.f32x2 %0, %1, %2, %3;" : "=l"(d) : "l"(a), "l"(b), "l"(c)); return d;
}
__device__ __forceinline__ u64 add2(u64 a, u64 b) {
    u64 d; asm("add.rn.f32x2 %0, %1, %2;" : "=l"(d) : "l"(a), "l"(b)); return d;
}
__device__ __forceinline__ u64 mul2(u64 a, u64 b) {
    u64 d; asm("mul.rn.f32x2 %0, %1, %2;" : "=l"(d) : "l"(a), "l"(b)); return d;
}
__device__ __forceinline__ u64 wsum2(u64 v) {
    #pragma unroll
    for (int o = 16; o; o >>= 1) v = add2(v, __shfl_xor_sync(0xffffffffu, v, o));
    return v;
}

#define CE(a, b)  { float _h = fmaxf(a, b); b = fminf(a, b); a = _h; }

__device__ __forceinline__ void ins5(float& a0, float& a1, float& a2, float& a3,
                                     float& a4, float v) {
    CE(a0, v); CE(a1, v); CE(a2, v); CE(a3, v); a4 = fmaxf(a4, v);
}

__device__ __forceinline__ void prefetch_row(float* buf, const float* src, int tid) {
    unsigned int base = (unsigned int)__cvta_generic_to_shared(buf);
    #pragma unroll
    for (int k = 0; k < 4; k++) {
        int idx = tid + k * 512;
        if (idx < 2000)
            asm volatile("cp.async.cg.shared.global [%0], [%1], 16;"
                         :: "r"(base + idx * 16), "l"(src + idx * 4) : "memory");
    }
}

// ---------------------------------------------------------------------------
// Kernel 1: persistent feature extraction. 444 blocks x 512 threads,
// double-buffered cp.async prefetch; compute phases identical to R5.
// Dynamic smem layout (floats):
//   buf0 @0, buf1 @8000, smp @16000, slmp2 @17000,
//   redA @18000 (32), wq @18032 (64), wtop @18096 (80), sfeat @18176 (64)
// ---------------------------------------------------------------------------
__global__ __launch_bounds__(512, 3) void feat_kernel(
    const float* __restrict__ post, float* __restrict__ feats_out)
{
    extern __shared__ __align__(16) float smem[];
    float* buf0   = smem;
    float* buf1   = smem + 8000;
    float* smp    = smem + 16000;
    float* slmp2  = smem + 17000;
    float (*redA)[2] = reinterpret_cast<float(*)[2]>(smem + 18000);
    float (*wq)[4]   = reinterpret_cast<float(*)[4]>(smem + 18032);
    float (*wtop)[5] = reinterpret_cast<float(*)[5]>(smem + 18096);
    float* sfeat  = smem + 18176;

    const int tid  = threadIdx.x;
    const int w    = tid >> 5;
    const int lane = tid & 31;

    const float4* m4c = reinterpret_cast<const float4*>(smp);
    const float4* l4c = reinterpret_cast<const float4*>(slmp2);

    int row = blockIdx.x;
    int cur = 0;
    if (row < BQ) prefetch_row(buf0, post + (size_t)row * (EE * CC), tid);
    asm volatile("cp.async.commit_group;" ::: "memory");

    for (; row < BQ; row += FEAT_BLOCKS) {
        float* sp = cur ? buf1 : buf0;
        {
            int nrow = row + FEAT_BLOCKS;
            if (nrow < BQ)
                prefetch_row(cur ? buf0 : buf1, post + (size_t)nrow * (EE * CC), tid);
            asm volatile("cp.async.commit_group;" ::: "memory");
            asm volatile("cp.async.wait_group 1;" ::: "memory");
        }
        __syncthreads();

        // ---- phase A1: class means, log2-means ----
        {
            float ment2 = 0.f, mn2 = 0.f;
            if (tid < 500) {
                const u64* spU = reinterpret_cast<const u64*>(sp);
                u64 a = spU[tid];
                #pragma unroll
                for (int e = 1; e < EE; e++) a = add2(a, spU[e * 500 + tid]);
                u64 mp2 = mul2(a, pk2(0.125f, 0.125f));
                float mx, my; upk2(mp2, mx, my);
                float lx = __log2f(mx + EPSF), ly = __log2f(my + EPSF);
                reinterpret_cast<u64*>(smp)[tid]   = mp2;
                reinterpret_cast<u64*>(slmp2)[tid] = pk2(lx, ly);
                ment2 = fmaf(mx, lx, 0.f); ment2 = fmaf(my, ly, ment2);
                mn2   = fmaf(mx, mx, 0.f); mn2   = fmaf(my, my, mn2);
            }
            ment2 = wsum(ment2); mn2 = wsum(mn2);
            if (lane == 0) { redA[w][0] = ment2; redA[w][1] = mn2; }
        }
        __syncthreads();

        // ---- phase A2: per-expert sums + top-5 (sort4 + staircase) ----
        {
            const int e = w & 7;
            const int h = w >> 3;
            const float4* p4 = reinterpret_cast<const float4*>(sp + e * CC);

            float A = 0.f;
            u64 SQ2 = 0ull, DOT2 = 0ull, B2 = 0ull;
            float a0 = 0.f, a1 = 0.f, a2 = 0.f, a3 = 0.f, a4 = 0.f;

            const int base = h * 125 + lane;
            #pragma unroll
            for (int it = 0; it < 4; it++) {
                if (it < 3 || lane < 29) {
                    int i = base + it * 32;
                    float4 p  = p4[i];
                    float4 mm = m4c[i];
                    float4 lm = l4c[i];
                    u64 pa = pk2(p.x, p.y), pb = pk2(p.z, p.w);
                    SQ2  = fma2(pa, pa, SQ2);               SQ2  = fma2(pb, pb, SQ2);
                    DOT2 = fma2(pa, pk2(mm.x, mm.y), DOT2); DOT2 = fma2(pb, pk2(mm.z, mm.w), DOT2);
                    B2   = fma2(pa, pk2(lm.x, lm.y), B2);   B2   = fma2(pb, pk2(lm.z, lm.w), B2);
                    float lx = __log2f(p.x + EPSF);
                    float ly = __log2f(p.y + EPSF);
                    float lz = __log2f(p.z + EPSF);
                    float lw = __log2f(p.w + EPSF);
                    A = fmaf(p.x, lx, A); A = fmaf(p.y, ly, A);
                    A = fmaf(p.z, lz, A); A = fmaf(p.w, lw, A);

                    float v0 = p.x, v1 = p.y, v2 = p.z, v3 = p.w;
                    CE(v0, v1); CE(v2, v3); CE(v0, v2); CE(v1, v3); CE(v1, v2);
                    CE(a0, v0); CE(a1, v0); CE(a2, v0); CE(a3, v0); a4 = fmaxf(a4, v0);
                    CE(a1, v1); CE(a2, v1); CE(a3, v1); a4 = fmaxf(a4, v1);
                    CE(a2, v2); CE(a3, v2); a4 = fmaxf(a4, v2);
                    CE(a3, v3); a4 = fmaxf(a4, v3);
                }
            }

            float sqa, sqb, da, db, ba, bb;
            upk2(SQ2, sqa, sqb); upk2(DOT2, da, db); upk2(B2, ba, bb);
            float SQ = sqa + sqb, DOT = da + db, B = ba + bb;

            A = wsum(A); B = wsum(B); SQ = wsum(SQ); DOT = wsum(DOT);

            float top[5];
            int ptr = 0;
            #pragma unroll
            for (int k = 0; k < 5; k++) {
                float v = a0;
                if      (ptr == 1) v = a1;
                else if (ptr == 2) v = a2;
                else if (ptr == 3) v = a3;
                else if (ptr == 4) v = a4;
                else if (ptr >= 5) v = 0.f;
                unsigned uv = __float_as_uint(v);
                unsigned um = __reduce_max_sync(0xffffffffu, uv);
                top[k] = __uint_as_float(um);
                unsigned msk = __ballot_sync(0xffffffffu, uv == um);
                if (lane == (__ffs(msk) - 1)) ptr++;
            }

            if (lane == 0) {
                wq[w][0] = A; wq[w][1] = B; wq[w][2] = SQ; wq[w][3] = DOT;
                wtop[w][0] = top[0]; wtop[w][1] = top[1]; wtop[w][2] = top[2];
                wtop[w][3] = top[3]; wtop[w][4] = top[4];
            }
        }
        __syncthreads();

        if (tid < EE) {
            int e = tid;
            float A   = wq[e][0] + wq[e + 8][0];
            float B   = wq[e][1] + wq[e + 8][1];
            float SQ  = wq[e][2] + wq[e + 8][2];
            float DOT = wq[e][3] + wq[e + 8][3];
            float t0 = wtop[e][0], t1 = wtop[e][1], t2 = wtop[e][2],
                  t3 = wtop[e][3], t4 = wtop[e][4];
            ins5(t0, t1, t2, t3, t4, wtop[e + 8][0]);
            ins5(t0, t1, t2, t3, t4, wtop[e + 8][1]);
            ins5(t0, t1, t2, t3, t4, wtop[e + 8][2]);
            ins5(t0, t1, t2, t3, t4, wtop[e + 8][3]);
            ins5(t0, t1, t2, t3, t4, wtop[e + 8][4]);

            float mn2T = 0.f;
            #pragma unroll
            for (int i = 0; i < 16; i++) mn2T += redA[i][1];
            float mn = fmaxf(sqrtf(mn2T), EPSF);
            float pn = fmaxf(sqrtf(SQ), EPSF);
            float tkm = t0 + t1 + t2 + t3 + t4;

            sfeat[e]      = -LN2F * A;
            sfeat[8 + e]  = tkm;
            sfeat[16 + e] = 1.0f - tkm;
            sfeat[24 + e] = t0;
            sfeat[32 + e] = t0 - t1;
            sfeat[40 + e] = DOT / (pn * mn);
            sfeat[48 + e] = LN2F * (A - B);
        }
        __syncthreads();

        if (tid == 0) {
            float ment2T = 0.f, mn2T = 0.f, SQall = 0.f;
            #pragma unroll
            for (int i = 0; i < 16; i++) {
                ment2T += redA[i][0];
                mn2T   += redA[i][1];
                SQall  += wq[i][2];
            }
            sfeat[56] = -LN2F * ment2T;
            sfeat[57] = (SQall - 8.0f * mn2T) * (1.0f / 7000.0f);
            float mm = 0.f;
            #pragma unroll
            for (int e = 0; e < EE; e++) mm += sfeat[24 + e];
            mm *= 0.125f;
            float sv = 0.f;
            #pragma unroll
            for (int e = 0; e < EE; e++) { float d = sfeat[24 + e] - mm; sv = fmaf(d, d, sv); }
            sfeat[58] = sqrtf(sv * (1.0f / 7.0f));
        }
        __syncthreads();

        if (tid < DD) {
            float v = sfeat[tid];
            v = fminf(fmaxf(v, -100.0f), 100.0f);
            feats_out[(size_t)row * DD + tid] = v;
        }
        __syncthreads();
        cur ^= 1;
    }
}

// ---------------------------------------------------------------------------
// Kernel 2: MLP (R5 exact, 79.6us proven).
// ---------------------------------------------------------------------------
__global__ __launch_bounds__(256, 7) void mlp_kernel(
    const float* __restrict__ feats,
    const float* __restrict__ W1, const float* __restrict__ b1,
    const float* __restrict__ g1, const float* __restrict__ be1,
    const float* __restrict__ W2, const float* __restrict__ b2,
    const float* __restrict__ g2, const float* __restrict__ be2,
    const float* __restrict__ W3, const float* __restrict__ b3,
    float* __restrict__ wout, float* __restrict__ lout)
{
    __shared__ __align__(16) char smraw[28288];
    u64*   sh1tU = (u64*)(smraw);
    u64*   sh2tU = (u64*)(smraw + 18432);
    u64*   sftU  = (u64*)(smraw + 18432);
    float* sftF  = (float*)(smraw + 18432);
    u64*   negmu = (u64*)(smraw + 27648);
    u64*   srs   = (u64*)(smraw + 27712);
    float* slog  = (float*)(smraw + 27776);

    const int tid  = threadIdx.x;
    const int rb   = blockIdx.x * MROWS;
    const int w    = tid >> 5;
    const int lane = tid & 31;

    for (int i = tid; i < MROWS * DD; i += 256) {
        int r = i / DD, d = i - r * DD;
        sftF[d * 16 + r] = feats[(size_t)rb * DD + i];
    }
    __syncthreads();

    const int ng = tid >> 1;
    const int rg = tid & 1;
    {
        u64 acc[2][4];
        #pragma unroll
        for (int i = 0; i < 2; i++)
            #pragma unroll
            for (int m = 0; m < 4; m++) acc[i][m] = 0ull;

        const float2* w1p = reinterpret_cast<const float2*>(W1 + ng * 2);
        const u64* fp = sftU + rg * 4;
        for (int d = 0; d < DD; d++) {
            float2 wv = w1p[d * (H1N / 2)];
            u64 w0 = pk2(wv.x, wv.x), w1v = pk2(wv.y, wv.y);
            u64 f0 = fp[d * 8 + 0], f1 = fp[d * 8 + 1];
            u64 f2 = fp[d * 8 + 2], f3 = fp[d * 8 + 3];
            acc[0][0] = fma2(f0, w0, acc[0][0]); acc[0][1] = fma2(f1, w0, acc[0][1]);
            acc[0][2] = fma2(f2, w0, acc[0][2]); acc[0][3] = fma2(f3, w0, acc[0][3]);
            acc[1][0] = fma2(f0, w1v, acc[1][0]); acc[1][1] = fma2(f1, w1v, acc[1][1]);
            acc[1][2] = fma2(f2, w1v, acc[1][2]); acc[1][3] = fma2(f3, w1v, acc[1][3]);
        }
        float2 bb = *reinterpret_cast<const float2*>(b1 + ng * 2);
        #pragma unroll
        for (int i = 0; i < 2; i++) {
            float b = i ? bb.y : bb.x;
            u64 bp = pk2(b, b);
            #pragma unroll
            for (int m = 0; m < 4; m++)
                sh1tU[(ng * 2 + i) * 9 + rg * 4 + m] = add2(acc[i][m], bp);
        }
    }
    __syncthreads();

    {
        u64 s = 0ull, q = 0ull;
        #pragma unroll
        for (int m = 0; m < 8; m++) {
            u64 v = sh1tU[(lane + 32 * m) * 9 + w];
            s = add2(s, v);
            q = fma2(v, v, q);
        }
        s = wsum2(s); q = wsum2(q);
        if (lane == 0) {
            float sa, sb, qa, qb;
            upk2(s, sa, sb); upk2(q, qa, qb);
            float mua = sa * (1.0f / H1N), mub = sb * (1.0f / H1N);
            float rsa = rsqrtf(qa * (1.0f / H1N) - mua * mua + LN_EPSF);
            float rsb = rsqrtf(qb * (1.0f / H1N) - mub * mub + LN_EPSF);
            negmu[w] = pk2(-mua, -mub);
            srs[w]   = pk2(rsa, rsb);
        }
    }
    __syncthreads();

    {
        float2 gg = *reinterpret_cast<const float2*>(g1 + ng * 2);
        float2 be = *reinterpret_cast<const float2*>(be1 + ng * 2);
        #pragma unroll
        for (int i = 0; i < 2; i++) {
            float g = i ? gg.y : gg.x;
            float b = i ? be.y : be.x;
            u64 gp = pk2(g, g), bp = pk2(b, b);
            int j = ng * 2 + i;
            #pragma unroll
            for (int m = 0; m < 4; m++) {
                int rp = rg * 4 + m;
                u64 t = add2(sh1tU[j * 9 + rp], negmu[rp]);
                t = mul2(t, srs[rp]);
                t = fma2(t, gp, bp);
                float x, y; upk2(t, x, y);
                sh1tU[j * 9 + rp] = pk2(fmaxf(x, 0.f), fmaxf(y, 0.f));
            }
        }
    }
    __syncthreads();

    const int half = tid >> 7;
    const int t2   = tid & 127;
    const int jg   = t2 >> 1;
    const int rg2  = t2 & 1;
    {
        u64 acc[2][4];
        #pragma unroll
        for (int i = 0; i < 2; i++)
            #pragma unroll
            for (int m = 0; m < 4; m++) acc[i][m] = 0ull;

        const int k0 = half * 128;
        const float2* w2p = reinterpret_cast<const float2*>(W2 + jg * 2);
        const u64* hp = sh1tU + rg2 * 4;
        for (int kk = 0; kk < 128; kk++) {
            int k = k0 + kk;
            float2 wv = w2p[k * (H2N / 2)];
            u64 w0 = pk2(wv.x, wv.x), w1v = pk2(wv.y, wv.y);
            u64 f0 = hp[k * 9 + 0], f1 = hp[k * 9 + 1];
            u64 f2 = hp[k * 9 + 2], f3 = hp[k * 9 + 3];
            acc[0][0] = fma2(f0, w0, acc[0][0]); acc[0][1] = fma2(f1, w0, acc[0][1]);
            acc[0][2] = fma2(f2, w0, acc[0][2]); acc[0][3] = fma2(f3, w0, acc[0][3]);
            acc[1][0] = fma2(f0, w1v, acc[1][0]); acc[1][1] = fma2(f1, w1v, acc[1][1]);
            acc[1][2] = fma2(f2, w1v, acc[1][2]); acc[1][3] = fma2(f3, w1v, acc[1][3]);
        }
        if (half) {
            #pragma unroll
            for (int i = 0; i < 2; i++)
                #pragma unroll
                for (int m = 0; m < 4; m++)
                    sh2tU[(jg * 2 + i) * 9 + rg2 * 4 + m] = acc[i][m];
        }
        __syncthreads();
        if (!half) {
            float2 bb = *reinterpret_cast<const float2*>(b2 + jg * 2);
            #pragma unroll
            for (int i = 0; i < 2; i++) {
                float b = i ? bb.y : bb.x;
                u64 bp = pk2(b, b);
                int j = jg * 2 + i;
                #pragma unroll
                for (int m = 0; m < 4; m++) {
                    int rp = rg2 * 4 + m;
                    sh2tU[j * 9 + rp] = add2(add2(acc[i][m], sh2tU[j * 9 + rp]), bp);
                }
            }
        }
    }
    __syncthreads();

    {
        u64 s = 0ull, q = 0ull;
        #pragma unroll
        for (int m = 0; m < 4; m++) {
            u64 v = sh2tU[(lane + 32 * m) * 9 + w];
            s = add2(s, v);
            q = fma2(v, v, q);
        }
        s = wsum2(s); q = wsum2(q);
        if (lane == 0) {
            float sa, sb, qa, qb;
            upk2(s, sa, sb); upk2(q, qa, qb);
            float mua = sa * (1.0f / H2N), mub = sb * (1.0f / H2N);
            float rsa = rsqrtf(qa * (1.0f / H2N) - mua * mua + LN_EPSF);
            float rsb = rsqrtf(qb * (1.0f / H2N) - mub * mub + LN_EPSF);
            negmu[w] = pk2(-mua, -mub);
            srs[w]   = pk2(rsa, rsb);
        }
    }
    __syncthreads();

    if (!half) {
        float2 gg = *reinterpret_cast<const float2*>(g2 + jg * 2);
        float2 be = *reinterpret_cast<const float2*>(be2 + jg * 2);
        #pragma unroll
        for (int i = 0; i < 2; i++) {
            float g = i ? gg.y : gg.x;
            float b = i ? be.y : be.x;
            u64 gp = pk2(g, g), bp = pk2(b, b);
            int j = jg * 2 + i;
            #pragma unroll
            for (int m = 0; m < 4; m++) {
                int rp = rg2 * 4 + m;
                u64 t = add2(sh2tU[j * 9 + rp], negmu[rp]);
                t = mul2(t, srs[rp]);
                t = fma2(t, gp, bp);
                float x, y; upk2(t, x, y);
                sh2tU[j * 9 + rp] = pk2(fmaxf(x, 0.f), fmaxf(y, 0.f));
            }
        }
    }
    __syncthreads();

    if (tid < 64) {
        int rp = tid >> 3, e = tid & 7;
        float b = b3[e];
        u64 acc = pk2(b, b);
        #pragma unroll 4
        for (int k = 0; k < H2N; k++) {
            float w3 = W3[k * EE + e];
            acc = fma2(sh2tU[k * 9 + rp], pk2(w3, w3), acc);
        }
        float la, lb; upk2(acc, la, lb);
        lout[(size_t)(rb + 2 * rp) * EE + e]     = la;
        lout[(size_t)(rb + 2 * rp + 1) * EE + e] = lb;
        slog[(2 * rp) * 8 + e]     = la;
        slog[(2 * rp + 1) * 8 + e] = lb;
    }
    __syncthreads();

    if (tid < MROWS) {
        int r = tid;
        float mx = -1e30f;
        #pragma unroll
        for (int e = 0; e < EE; e++) mx = fmaxf(mx, slog[r * 8 + e]);
        float ex[EE]; float s = 0.f;
        #pragma unroll
        for (int e = 0; e < EE; e++) { ex[e] = __expf(slog[r * 8 + e] - mx); s += ex[e]; }
        float inv = 1.0f / s;
        #pragma unroll
        for (int e = 0; e < EE; e++) wout[(size_t)(rb + r) * EE + e] = ex[e] * inv;
    }
}

// diagnostic no-op launches to shift ncu's -s 5 capture onto feat_kernel
__global__ void dummy_kernel() {}

extern "C" void kernel_launch(void* const* d_in, const int* in_sizes, int n_in,
                              void* d_out, int out_size)
{
    const float* post = (const float*)d_in[0];
    const float* W1   = (const float*)d_in[1];
    const float* b1   = (const float*)d_in[2];
    const float* g1   = (const float*)d_in[3];
    const float* be1  = (const float*)d_in[4];
    const float* W2   = (const float*)d_in[5];
    const float* b2   = (const float*)d_in[6];
    const float* g2   = (const float*)d_in[7];
    const float* be2  = (const float*)d_in[8];
    const float* W3   = (const float*)d_in[9];
    const float* b3   = (const float*)d_in[10];

    float* out  = (float*)d_out;
    float* wout = out;                         // weights (B, 8)
    float* lout = out + (size_t)BQ * EE;       // logits  (B, 8)
    float* fout = out + (size_t)BQ * EE * 2;   // feats   (B, 59)

    cudaFuncSetAttribute(feat_kernel, cudaFuncAttributeMaxDynamicSharedMemorySize,
                         FEAT_SMEM);

    feat_kernel<<<FEAT_BLOCKS, 512, FEAT_SMEM>>>(post, fout);
    mlp_kernel<<<BQ / MROWS, 256>>>(fout, W1, b1, g1, be1,
                                    W2, b2, g2, be2, W3, b3,
                                    wout, lout);
    dummy_kernel<<<1, 32>>>();
    dummy_kernel<<<1, 32>>>();
    dummy_kernel<<<1, 32>>>();
}

// round 15
// speedup vs baseline: 1.8189x; 1.8189x over previous
#include <cuda_runtime.h>

#define BQ 16384
#define EE 8
#define CC 1000
#define DD 59
#define H1N 256
#define H2N 128
#define EPSF 1e-8f
#define LN_EPSF 1e-5f
#define MROWS 16
#define LN2F 0.69314718055994530942f

typedef unsigned long long u64;

__device__ __forceinline__ float wsum(float v) {
    #pragma unroll
    for (int o = 16; o; o >>= 1) v += __shfl_xor_sync(0xffffffffu, v, o);
    return v;
}

// ---- f32x2 packed helpers (sm_100+) ----
__device__ __forceinline__ u64 pk2(float a, float b) {
    u64 r; asm("mov.b64 %0, {%1, %2};" : "=l"(r) : "f"(a), "f"(b)); return r;
}
__device__ __forceinline__ void upk2(u64 v, float& a, float& b) {
    asm("mov.b64 {%0, %1}, %2;" : "=f"(a), "=f"(b) : "l"(v));
}
__device__ __forceinline__ u64 fma2(u64 a, u64 b, u64 c) {
    u64 d; asm("fma.rn.f32x2 %0, %1, %2, %3;" : "=l"(d) : "l"(a), "l"(b), "l"(c)); return d;
}
__device__ __forceinline__ u64 add2(u64 a, u64 b) {
    u64 d; asm("add.rn.f32x2 %0, %1, %2;" : "=l"(d) : "l"(a), "l"(b)); return d;
}
__device__ __forceinline__ u64 mul2(u64 a, u64 b) {
    u64 d; asm("mul.rn.f32x2 %0, %1, %2;" : "=l"(d) : "l"(a), "l"(b)); return d;
}
__device__ __forceinline__ u64 wsum2(u64 v) {
    #pragma unroll
    for (int o = 16; o; o >>= 1) v = add2(v, __shfl_xor_sync(0xffffffffu, v, o));
    return v;
}

#define CE(a, b)  { float _h = fmaxf(a, b); b = fminf(a, b); a = _h; }

__device__ __forceinline__ void ins5(float& a0, float& a1, float& a2, float& a3,
                                     float& a4, float v) {
    CE(a0, v); CE(a1, v); CE(a2, v); CE(a3, v); a4 = fmaxf(a4, v);
}

// ---------------------------------------------------------------------------
// Kernel 1: feature extraction (R5 exact). One block per row, 512 threads.
// ---------------------------------------------------------------------------
__global__ __launch_bounds__(512, 3) void feat_kernel(
    const float* __restrict__ post, float* __restrict__ feats_out)
{
    __shared__ __align__(16) float sp[EE * CC];
    __shared__ __align__(16) float smp[CC];
    __shared__ __align__(16) float slmp2[CC];
    __shared__ float redA[16][2];
    __shared__ float wq[16][4];
    __shared__ float wtop[16][5];
    __shared__ float sfeat[DD];

    const int tid  = threadIdx.x;
    const int row  = blockIdx.x;
    const int w    = tid >> 5;
    const int lane = tid & 31;

    {
        const float4* src = reinterpret_cast<const float4*>(post + (size_t)row * (EE * CC));
        float4* dst = reinterpret_cast<float4*>(sp);
        #pragma unroll
        for (int i = 0; i < 4; i++) {
            int idx = tid + i * 512;
            if (idx < (EE * CC) / 4) dst[idx] = src[idx];
        }
    }
    __syncthreads();

    // ---- phase A1: class means, log2-means ----
    {
        float ment2 = 0.f, mn2 = 0.f;
        if (tid < 500) {
            const u64* spU = reinterpret_cast<const u64*>(sp);
            u64 a = spU[tid];
            #pragma unroll
            for (int e = 1; e < EE; e++) a = add2(a, spU[e * 500 + tid]);
            u64 mp2 = mul2(a, pk2(0.125f, 0.125f));
            float mx, my; upk2(mp2, mx, my);
            float lx = __log2f(mx + EPSF), ly = __log2f(my + EPSF);
            reinterpret_cast<u64*>(smp)[tid]   = mp2;
            reinterpret_cast<u64*>(slmp2)[tid] = pk2(lx, ly);
            ment2 = fmaf(mx, lx, 0.f); ment2 = fmaf(my, ly, ment2);
            mn2   = fmaf(mx, mx, 0.f); mn2   = fmaf(my, my, mn2);
        }
        ment2 = wsum(ment2); mn2 = wsum(mn2);
        if (lane == 0) { redA[w][0] = ment2; redA[w][1] = mn2; }
    }
    __syncthreads();

    // ---- phase A2: per-expert sums + top-5 (sort4 + staircase) ----
    {
        const int e = w & 7;
        const int h = w >> 3;
        const float4* p4 = reinterpret_cast<const float4*>(sp + e * CC);
        const float4* m4 = reinterpret_cast<const float4*>(smp);
        const float4* l4 = reinterpret_cast<const float4*>(slmp2);

        float A = 0.f;
        u64 SQ2 = 0ull, DOT2 = 0ull, B2 = 0ull;
        float a0 = 0.f, a1 = 0.f, a2 = 0.f, a3 = 0.f, a4 = 0.f;

        const int base = h * 125 + lane;
        #pragma unroll
        for (int it = 0; it < 4; it++) {
            if (it < 3 || lane < 29) {
                int i = base + it * 32;
                float4 p  = p4[i];
                float4 mm = m4[i];
                float4 lm = l4[i];
                u64 pa = pk2(p.x, p.y), pb = pk2(p.z, p.w);
                SQ2  = fma2(pa, pa, SQ2);               SQ2  = fma2(pb, pb, SQ2);
                DOT2 = fma2(pa, pk2(mm.x, mm.y), DOT2); DOT2 = fma2(pb, pk2(mm.z, mm.w), DOT2);
                B2   = fma2(pa, pk2(lm.x, lm.y), B2);   B2   = fma2(pb, pk2(lm.z, lm.w), B2);
                float lx = __log2f(p.x + EPSF);
                float ly = __log2f(p.y + EPSF);
                float lz = __log2f(p.z + EPSF);
                float lw = __log2f(p.w + EPSF);
                A = fmaf(p.x, lx, A); A = fmaf(p.y, ly, A);
                A = fmaf(p.z, lz, A); A = fmaf(p.w, lw, A);

                float v0 = p.x, v1 = p.y, v2 = p.z, v3 = p.w;
                CE(v0, v1); CE(v2, v3); CE(v0, v2); CE(v1, v3); CE(v1, v2);
                CE(a0, v0); CE(a1, v0); CE(a2, v0); CE(a3, v0); a4 = fmaxf(a4, v0);
                CE(a1, v1); CE(a2, v1); CE(a3, v1); a4 = fmaxf(a4, v1);
                CE(a2, v2); CE(a3, v2); a4 = fmaxf(a4, v2);
                CE(a3, v3); a4 = fmaxf(a4, v3);
            }
        }

        float sqa, sqb, da, db, ba, bb;
        upk2(SQ2, sqa, sqb); upk2(DOT2, da, db); upk2(B2, ba, bb);
        float SQ = sqa + sqb, DOT = da + db, B = ba + bb;

        A = wsum(A); B = wsum(B); SQ = wsum(SQ); DOT = wsum(DOT);

        // warp top-5 pop-merge via redux (all values >= 0)
        float top[5];
        int ptr = 0;
        #pragma unroll
        for (int k = 0; k < 5; k++) {
            float v = a0;
            if      (ptr == 1) v = a1;
            else if (ptr == 2) v = a2;
            else if (ptr == 3) v = a3;
            else if (ptr == 4) v = a4;
            else if (ptr >= 5) v = 0.f;
            unsigned uv = __float_as_uint(v);
            unsigned um = __reduce_max_sync(0xffffffffu, uv);
            top[k] = __uint_as_float(um);
            unsigned msk = __ballot_sync(0xffffffffu, uv == um);
            if (lane == (__ffs(msk) - 1)) ptr++;
        }

        if (lane == 0) {
            wq[w][0] = A; wq[w][1] = B; wq[w][2] = SQ; wq[w][3] = DOT;
            wtop[w][0] = top[0]; wtop[w][1] = top[1]; wtop[w][2] = top[2];
            wtop[w][3] = top[3]; wtop[w][4] = top[4];
        }
    }
    __syncthreads();

    if (tid < EE) {
        int e = tid;
        float A   = wq[e][0] + wq[e + 8][0];
        float B   = wq[e][1] + wq[e + 8][1];
        float SQ  = wq[e][2] + wq[e + 8][2];
        float DOT = wq[e][3] + wq[e + 8][3];
        float t0 = wtop[e][0], t1 = wtop[e][1], t2 = wtop[e][2],
              t3 = wtop[e][3], t4 = wtop[e][4];
        ins5(t0, t1, t2, t3, t4, wtop[e + 8][0]);
        ins5(t0, t1, t2, t3, t4, wtop[e + 8][1]);
        ins5(t0, t1, t2, t3, t4, wtop[e + 8][2]);
        ins5(t0, t1, t2, t3, t4, wtop[e + 8][3]);
        ins5(t0, t1, t2, t3, t4, wtop[e + 8][4]);

        float mn2T = 0.f;
        #pragma unroll
        for (int i = 0; i < 16; i++) mn2T += redA[i][1];
        float mn = fmaxf(sqrtf(mn2T), EPSF);
        float pn = fmaxf(sqrtf(SQ), EPSF);
        float tkm = t0 + t1 + t2 + t3 + t4;

        sfeat[e]      = -LN2F * A;
        sfeat[8 + e]  = tkm;
        sfeat[16 + e] = 1.0f - tkm;
        sfeat[24 + e] = t0;
        sfeat[32 + e] = t0 - t1;
        sfeat[40 + e] = DOT / (pn * mn);
        sfeat[48 + e] = LN2F * (A - B);
    }
    __syncthreads();

    if (tid == 0) {
        float ment2T = 0.f, mn2T = 0.f, SQall = 0.f;
        #pragma unroll
        for (int i = 0; i < 16; i++) {
            ment2T += redA[i][0];
            mn2T   += redA[i][1];
            SQall  += wq[i][2];
        }
        sfeat[56] = -LN2F * ment2T;
        sfeat[57] = (SQall - 8.0f * mn2T) * (1.0f / 7000.0f);
        float mm = 0.f;
        #pragma unroll
        for (int e = 0; e < EE; e++) mm += sfeat[24 + e];
        mm *= 0.125f;
        float sv = 0.f;
        #pragma unroll
        for (int e = 0; e < EE; e++) { float d = sfeat[24 + e] - mm; sv = fmaf(d, d, sv); }
        sfeat[58] = sqrtf(sv * (1.0f / 7.0f));
    }
    __syncthreads();

    if (tid < DD) {
        float v = sfeat[tid];
        v = fminf(fmaxf(v, -100.0f), 100.0f);
        feats_out[(size_t)row * DD + tid] = v;
    }
}

// ---------------------------------------------------------------------------
// Kernel 2: MLP (R5 exact + unroll hints). 16 rows/block, 256 threads,
// grid 1024, stride-9 u64, 28.3KB smem, 7 blocks/SM single wave.
// ---------------------------------------------------------------------------
__global__ __launch_bounds__(256, 7) void mlp_kernel(
    const float* __restrict__ feats,
    const float* __restrict__ W1, const float* __restrict__ b1,
    const float* __restrict__ g1, const float* __restrict__ be1,
    const float* __restrict__ W2, const float* __restrict__ b2,
    const float* __restrict__ g2, const float* __restrict__ be2,
    const float* __restrict__ W3, const float* __restrict__ b3,
    float* __restrict__ wout, float* __restrict__ lout)
{
    __shared__ __align__(16) char smraw[28288];
    u64*   sh1tU = (u64*)(smraw);
    u64*   sh2tU = (u64*)(smraw + 18432);
    u64*   sftU  = (u64*)(smraw + 18432);
    float* sftF  = (float*)(smraw + 18432);
    u64*   negmu = (u64*)(smraw + 27648);
    u64*   srs   = (u64*)(smraw + 27712);
    float* slog  = (float*)(smraw + 27776);

    const int tid  = threadIdx.x;
    const int rb   = blockIdx.x * MROWS;
    const int w    = tid >> 5;
    const int lane = tid & 31;

    for (int i = tid; i < MROWS * DD; i += 256) {
        int r = i / DD, d = i - r * DD;
        sftF[d * 16 + r] = feats[(size_t)rb * DD + i];
    }
    __syncthreads();

    // ---- layer 1: 2 neurons x 4 rowpairs per thread ----
    const int ng = tid >> 1;
    const int rg = tid & 1;
    {
        u64 acc[2][4];
        #pragma unroll
        for (int i = 0; i < 2; i++)
            #pragma unroll
            for (int m = 0; m < 4; m++) acc[i][m] = 0ull;

        const float2* w1p = reinterpret_cast<const float2*>(W1 + ng * 2);
        const u64* fp = sftU + rg * 4;
        #pragma unroll 2
        for (int d = 0; d < DD; d++) {
            float2 wv = w1p[d * (H1N / 2)];
            u64 w0 = pk2(wv.x, wv.x), w1v = pk2(wv.y, wv.y);
            u64 f0 = fp[d * 8 + 0], f1 = fp[d * 8 + 1];
            u64 f2 = fp[d * 8 + 2], f3 = fp[d * 8 + 3];
            acc[0][0] = fma2(f0, w0, acc[0][0]); acc[0][1] = fma2(f1, w0, acc[0][1]);
            acc[0][2] = fma2(f2, w0, acc[0][2]); acc[0][3] = fma2(f3, w0, acc[0][3]);
            acc[1][0] = fma2(f0, w1v, acc[1][0]); acc[1][1] = fma2(f1, w1v, acc[1][1]);
            acc[1][2] = fma2(f2, w1v, acc[1][2]); acc[1][3] = fma2(f3, w1v, acc[1][3]);
        }
        float2 bb = *reinterpret_cast<const float2*>(b1 + ng * 2);
        #pragma unroll
        for (int i = 0; i < 2; i++) {
            float b = i ? bb.y : bb.x;
            u64 bp = pk2(b, b);
            #pragma unroll
            for (int m = 0; m < 4; m++)
                sh1tU[(ng * 2 + i) * 9 + rg * 4 + m] = add2(acc[i][m], bp);
        }
    }
    __syncthreads();

    // ---- LN1 stats: warp w handles rowpair w ----
    {
        u64 s = 0ull, q = 0ull;
        #pragma unroll
        for (int m = 0; m < 8; m++) {
            u64 v = sh1tU[(lane + 32 * m) * 9 + w];
            s = add2(s, v);
            q = fma2(v, v, q);
        }
        s = wsum2(s); q = wsum2(q);
        if (lane == 0) {
            float sa, sb, qa, qb;
            upk2(s, sa, sb); upk2(q, qa, qb);
            float mua = sa * (1.0f / H1N), mub = sb * (1.0f / H1N);
            float rsa = rsqrtf(qa * (1.0f / H1N) - mua * mua + LN_EPSF);
            float rsb = rsqrtf(qb * (1.0f / H1N) - mub * mub + LN_EPSF);
            negmu[w] = pk2(-mua, -mub);
            srs[w]   = pk2(rsa, rsb);
        }
    }
    __syncthreads();

    // ---- LN1 apply + relu ----
    {
        float2 gg = *reinterpret_cast<const float2*>(g1 + ng * 2);
        float2 be = *reinterpret_cast<const float2*>(be1 + ng * 2);
        #pragma unroll
        for (int i = 0; i < 2; i++) {
            float g = i ? gg.y : gg.x;
            float b = i ? be.y : be.x;
            u64 gp = pk2(g, g), bp = pk2(b, b);
            int j = ng * 2 + i;
            #pragma unroll
            for (int m = 0; m < 4; m++) {
                int rp = rg * 4 + m;
                u64 t = add2(sh1tU[j * 9 + rp], negmu[rp]);
                t = mul2(t, srs[rp]);
                t = fma2(t, gp, bp);
                float x, y; upk2(t, x, y);
                sh1tU[j * 9 + rp] = pk2(fmaxf(x, 0.f), fmaxf(y, 0.f));
            }
        }
    }
    __syncthreads();

    // ---- layer 2: K=256 split in halves, 2 neurons x 4 rowpairs ----
    const int half = tid >> 7;
    const int t2   = tid & 127;
    const int jg   = t2 >> 1;
    const int rg2  = t2 & 1;
    {
        u64 acc[2][4];
        #pragma unroll
        for (int i = 0; i < 2; i++)
            #pragma unroll
            for (int m = 0; m < 4; m++) acc[i][m] = 0ull;

        const int k0 = half * 128;
        const float2* w2p = reinterpret_cast<const float2*>(W2 + jg * 2);
        const u64* hp = sh1tU + rg2 * 4;
        #pragma unroll 2
        for (int kk = 0; kk < 128; kk++) {
            int k = k0 + kk;
            float2 wv = w2p[k * (H2N / 2)];
            u64 w0 = pk2(wv.x, wv.x), w1v = pk2(wv.y, wv.y);
            u64 f0 = hp[k * 9 + 0], f1 = hp[k * 9 + 1];
            u64 f2 = hp[k * 9 + 2], f3 = hp[k * 9 + 3];
            acc[0][0] = fma2(f0, w0, acc[0][0]); acc[0][1] = fma2(f1, w0, acc[0][1]);
            acc[0][2] = fma2(f2, w0, acc[0][2]); acc[0][3] = fma2(f3, w0, acc[0][3]);
            acc[1][0] = fma2(f0, w1v, acc[1][0]); acc[1][1] = fma2(f1, w1v, acc[1][1]);
            acc[1][2] = fma2(f2, w1v, acc[1][2]); acc[1][3] = fma2(f3, w1v, acc[1][3]);
        }
        if (half) {
            #pragma unroll
            for (int i = 0; i < 2; i++)
                #pragma unroll
                for (int m = 0; m < 4; m++)
                    sh2tU[(jg * 2 + i) * 9 + rg2 * 4 + m] = acc[i][m];
        }
        __syncthreads();
        if (!half) {
            float2 bb = *reinterpret_cast<const float2*>(b2 + jg * 2);
            #pragma unroll
            for (int i = 0; i < 2; i++) {
                float b = i ? bb.y : bb.x;
                u64 bp = pk2(b, b);
                int j = jg * 2 + i;
                #pragma unroll
                for (int m = 0; m < 4; m++) {
                    int rp = rg2 * 4 + m;
                    sh2tU[j * 9 + rp] = add2(add2(acc[i][m], sh2tU[j * 9 + rp]), bp);
                }
            }
        }
    }
    __syncthreads();

    // ---- LN2 stats: warp w handles rowpair w ----
    {
        u64 s = 0ull, q = 0ull;
        #pragma unroll
        for (int m = 0; m < 4; m++) {
            u64 v = sh2tU[(lane + 32 * m) * 9 + w];
            s = add2(s, v);
            q = fma2(v, v, q);
        }
        s = wsum2(s); q = wsum2(q);
        if (lane == 0) {
            float sa, sb, qa, qb;
            upk2(s, sa, sb); upk2(q, qa, qb);
            float mua = sa * (1.0f / H2N), mub = sb * (1.0f / H2N);
            float rsa = rsqrtf(qa * (1.0f / H2N) - mua * mua + LN_EPSF);
            float rsb = rsqrtf(qb * (1.0f / H2N) - mub * mub + LN_EPSF);
            negmu[w] = pk2(-mua, -mub);
            srs[w]   = pk2(rsa, rsb);
        }
    }
    __syncthreads();

    // ---- LN2 apply + relu (half 0 only) ----
    if (!half) {
        float2 gg = *reinterpret_cast<const float2*>(g2 + jg * 2);
        float2 be = *reinterpret_cast<const float2*>(be2 + jg * 2);
        #pragma unroll
        for (int i = 0; i < 2; i++) {
            float g = i ? gg.y : gg.x;
            float b = i ? be.y : be.x;
            u64 gp = pk2(g, g), bp = pk2(b, b);
            int j = jg * 2 + i;
            #pragma unroll
            for (int m = 0; m < 4; m++) {
                int rp = rg2 * 4 + m;
                u64 t = add2(sh2tU[j * 9 + rp], negmu[rp]);
                t = mul2(t, srs[rp]);
                t = fma2(t, gp, bp);
                float x, y; upk2(t, x, y);
                sh2tU[j * 9 + rp] = pk2(fmaxf(x, 0.f), fmaxf(y, 0.f));
            }
        }
    }
    __syncthreads();

    // ---- layer 3: thread (rp, e), 64 threads ----
    if (tid < 64) {
        int rp = tid >> 3, e = tid & 7;
        float b = b3[e];
        u64 acc = pk2(b, b);
        #pragma unroll 4
        for (int k = 0; k < H2N; k++) {
            float w3 = W3[k * EE + e];
            acc = fma2(sh2tU[k * 9 + rp], pk2(w3, w3), acc);
        }
        float la, lb; upk2(acc, la, lb);
        lout[(size_t)(rb + 2 * rp) * EE + e]     = la;
        lout[(size_t)(rb + 2 * rp + 1) * EE + e] = lb;
        slog[(2 * rp) * 8 + e]     = la;
        slog[(2 * rp + 1) * 8 + e] = lb;
    }
    __syncthreads();

    // ---- softmax: thread per row ----
    if (tid < MROWS) {
        int r = tid;
        float mx = -1e30f;
        #pragma unroll
        for (int e = 0; e < EE; e++) mx = fmaxf(mx, slog[r * 8 + e]);
        float ex[EE]; float s = 0.f;
        #pragma unroll
        for (int e = 0; e < EE; e++) { ex[e] = __expf(slog[r * 8 + e] - mx); s += ex[e]; }
        float inv = 1.0f / s;
        #pragma unroll
        for (int e = 0; e < EE; e++) wout[(size_t)(rb + r) * EE + e] = ex[e] * inv;
    }
}

extern "C" void kernel_launch(void* const* d_in, const int* in_sizes, int n_in,
                              void* d_out, int out_size)
{
    const float* post = (const float*)d_in[0];
    const float* W1   = (const float*)d_in[1];
    const float* b1   = (const float*)d_in[2];
    const float* g1   = (const float*)d_in[3];
    const float* be1  = (const float*)d_in[4];
    const float* W2   = (const float*)d_in[5];
    const float* b2   = (const float*)d_in[6];
    const float* g2   = (const float*)d_in[7];
    const float* be2  = (const float*)d_in[8];
    const float* W3   = (const float*)d_in[9];
    const float* b3   = (const float*)d_in[10];

    float* out  = (float*)d_out;
    float* wout = out;                         // weights (B, 8)
    float* lout = out + (size_t)BQ * EE;       // logits  (B, 8)
    float* fout = out + (size_t)BQ * EE * 2;   // feats   (B, 59)

    feat_kernel<<<BQ, 512>>>(post, fout);
    mlp_kernel<<<BQ / MROWS, 256>>>(fout, W1, b1, g1, be1,
                                    W2, b2, g2, be2, W3, b3,
                                    wout, lout);
}